// round 5
// baseline (speedup 1.0000x reference)
#include <cuda_runtime.h>
#include <cstdint>

#define NN 50000
#define NE 600000
#define HF 128
#define NC 10
#define NBLK ((NN + 511) / 512)   // 98 scan blocks

// ---------------- scratch (static device globals; no allocation) ----------------
__device__ __align__(16) float d_g[(size_t)NN * HF];    // dinv*(xW^T+b)
__device__ __align__(16) float d_h[(size_t)NN * HF];    // conv output (h1 then h2)
__device__ int   d_deg[NN];      // row-degree + 1 (norm)
__device__ float d_dinv[NN];
__device__ int   d_cnt[NN];      // col histogram (CSR)
__device__ int   d_start[NN];    // CSR offsets
__device__ int   d_ptr[NN];      // CSR fill cursors
__device__ int   d_csr[NE];      // source row per CSR slot
__device__ int   d_bsum[128];    // scan block sums
__device__ int   d_boff[128];    // scan block offsets
__device__ float d_loss;

#define FFMA2(acc, a, b) asm("fma.rn.f32x2 %0, %1, %2, %0;" : "+l"(acc) : "l"(a), "l"(b))

// ---------------- init ----------------
__global__ void k_init() {
    int i = blockIdx.x * blockDim.x + threadIdx.x;
    if (i < NN) { d_deg[i] = 1; d_cnt[i] = 0; }
    if (i == 0) d_loss = 0.f;
}

// row-degree (norm) + col histogram (CSR) in one pass
__global__ void k_hist(const int* __restrict__ row, const int* __restrict__ col) {
    int e = blockIdx.x * blockDim.x + threadIdx.x;
    if (e < NE) {
        atomicAdd(&d_deg[row[e]], 1);
        atomicAdd(&d_cnt[col[e]], 1);
    }
}

__global__ void k_dinv() {
    int i = blockIdx.x * blockDim.x + threadIdx.x;
    if (i < NN) d_dinv[i] = rsqrtf((float)d_deg[i]);
}

// ---------------- multi-block exclusive scan of d_cnt ----------------
// phase 1: 98 blocks x 256 threads, 2 elements/thread -> local scan + block sums
__global__ void k_scan1() {
    __shared__ int wsum[8];
    const int t = threadIdx.x;
    const int base = blockIdx.x * 512 + t * 2;
    int c0 = (base < NN) ? d_cnt[base] : 0;
    int c1 = (base + 1 < NN) ? d_cnt[base + 1] : 0;
    int s = c0 + c1;
    int v = s;
#pragma unroll
    for (int o = 1; o < 32; o <<= 1) {
        int u = __shfl_up_sync(0xffffffffu, v, o);
        if ((t & 31) >= o) v += u;
    }
    if ((t & 31) == 31) wsum[t >> 5] = v;
    __syncthreads();
    if (t < 8) {
        int w = wsum[t];
#pragma unroll
        for (int o = 1; o < 8; o <<= 1) {
            int u = __shfl_up_sync(0xffu, w, o);
            if (t >= o) w += u;
        }
        wsum[t] = w;
    }
    __syncthreads();
    int pre = v - s + ((t >= 32) ? wsum[(t >> 5) - 1] : 0);
    if (base < NN) d_start[base] = pre;
    if (base + 1 < NN) d_start[base + 1] = pre + c0;
    if (t == 255) d_bsum[blockIdx.x] = wsum[7];
}

// phase 2: single warp scans the 98 block sums
__global__ void k_scan2() {
    const int l = threadIdx.x;
    int c[4];
    int s = 0;
#pragma unroll
    for (int i = 0; i < 4; i++) {
        int idx = l * 4 + i;
        c[i] = (idx < NBLK) ? d_bsum[idx] : 0;
        s += c[i];
    }
    int v = s;
#pragma unroll
    for (int o = 1; o < 32; o <<= 1) {
        int u = __shfl_up_sync(0xffffffffu, v, o);
        if (l >= o) v += u;
    }
    int ex = v - s;
#pragma unroll
    for (int i = 0; i < 4; i++) {
        int idx = l * 4 + i;
        if (idx < NBLK) d_boff[idx] = ex;
        ex += c[i];
    }
}

// phase 3: add block offsets, init fill cursors
__global__ void k_scan3() {
    int i = blockIdx.x * blockDim.x + threadIdx.x;
    if (i < NN) {
        int v = d_start[i] + d_boff[i >> 9];
        d_start[i] = v;
        d_ptr[i] = v;
    }
}

__global__ void k_fill(const int* __restrict__ row, const int* __restrict__ col) {
    int e = blockIdx.x * blockDim.x + threadIdx.x;
    if (e < NE) {
        int c = col[e];
        int slot = atomicAdd(&d_ptr[c], 1);
        d_csr[slot] = row[e];
    }
}

// ---------------- node GEMM (f32x2 packed): g = dinv * (x @ W^T + b) ----------------
// Block: 64 rows x 128 cols, 256 threads, thread = 8 rows x 4 cols.
// Shared staged as float2 k-pairs, stride 17 float2 (pad) per row.
__global__ void k_gemm(const float* __restrict__ x, const float* __restrict__ W,
                       const float* __restrict__ b) {
    __shared__ __align__(16) float2 xs2[64 * 17];
    __shared__ __align__(16) float2 ws2[128 * 17];
    const int tid = threadIdx.x;
    const int tc = tid & 31;
    const int tr = tid >> 5;
    const int rb = blockIdx.x * 64;

    unsigned long long acc2[8][4];
#pragma unroll
    for (int i = 0; i < 8; i++)
#pragma unroll
        for (int j = 0; j < 4; j++) acc2[i][j] = 0ull;

    for (int kc = 0; kc < HF; kc += 32) {
#pragma unroll
        for (int l = 0; l < 2; l++) {
            int idx = tid + l * 256;      // float4 index, 0..511
            int r = idx >> 3;
            int q = idx & 7;
            float4 v = make_float4(0.f, 0.f, 0.f, 0.f);
            if (rb + r < NN) v = *(const float4*)(x + (size_t)(rb + r) * HF + kc + q * 4);
            xs2[r * 17 + q * 2 + 0] = make_float2(v.x, v.y);
            xs2[r * 17 + q * 2 + 1] = make_float2(v.z, v.w);
        }
#pragma unroll
        for (int l = 0; l < 4; l++) {
            int idx = tid + l * 256;      // float4 index, 0..1023
            int t = idx >> 3;
            int q = idx & 7;
            float4 v = *(const float4*)(W + (size_t)t * HF + kc + q * 4);
            ws2[t * 17 + q * 2 + 0] = make_float2(v.x, v.y);
            ws2[t * 17 + q * 2 + 1] = make_float2(v.z, v.w);
        }
        __syncthreads();
#pragma unroll
        for (int kq = 0; kq < 16; kq++) {
            unsigned long long wv[4];
#pragma unroll
            for (int j = 0; j < 4; j++)
                wv[j] = *(const unsigned long long*)&ws2[(tc + 32 * j) * 17 + kq];
#pragma unroll
            for (int i = 0; i < 8; i++) {
                unsigned long long xv =
                    *(const unsigned long long*)&xs2[(tr * 8 + i) * 17 + kq];
#pragma unroll
                for (int j = 0; j < 4; j++) FFMA2(acc2[i][j], xv, wv[j]);
            }
        }
        __syncthreads();
    }

#pragma unroll
    for (int i = 0; i < 8; i++) {
        int r = rb + tr * 8 + i;
        if (r >= NN) break;
        float dv = d_dinv[r];
#pragma unroll
        for (int j = 0; j < 4; j++) {
            int c0 = tc + 32 * j;
            float lo, hi;
            asm("mov.b64 {%0, %1}, %2;" : "=f"(lo), "=f"(hi) : "l"(acc2[i][j]));
            d_g[(size_t)r * HF + c0] = dv * (lo + hi + b[c0]);
        }
    }
}

// ---------------- CSR aggregate: h[n] = dinv[n] * (g[n] + sum_{e: col=n} g[row_e]) ----------------
__global__ void k_aggr() {
    int gw = (blockIdx.x * blockDim.x + threadIdx.x) >> 5;
    if (gw >= NN) return;
    const int lane = threadIdx.x & 31;
    const int s = d_start[gw];
    const int cnt = d_cnt[gw];
    const float4* gp = (const float4*)d_g;

    float4 acc = __ldg(gp + (size_t)gw * 32 + lane);   // self loop
    for (int j0 = 0; j0 < cnt; j0 += 32) {
        int r = 0;
        if (j0 + lane < cnt) r = __ldg(d_csr + s + j0 + lane);
        int m = min(32, cnt - j0);
        int k = 0;
        for (; k + 4 <= m; k += 4) {
            int r0 = __shfl_sync(0xffffffffu, r, k + 0);
            int r1 = __shfl_sync(0xffffffffu, r, k + 1);
            int r2 = __shfl_sync(0xffffffffu, r, k + 2);
            int r3 = __shfl_sync(0xffffffffu, r, k + 3);
            float4 v0 = __ldg(gp + (size_t)r0 * 32 + lane);
            float4 v1 = __ldg(gp + (size_t)r1 * 32 + lane);
            float4 v2 = __ldg(gp + (size_t)r2 * 32 + lane);
            float4 v3 = __ldg(gp + (size_t)r3 * 32 + lane);
            acc.x += v0.x + v1.x + v2.x + v3.x;
            acc.y += v0.y + v1.y + v2.y + v3.y;
            acc.z += v0.z + v1.z + v2.z + v3.z;
            acc.w += v0.w + v1.w + v2.w + v3.w;
        }
        for (; k < m; k++) {
            int rr = __shfl_sync(0xffffffffu, r, k);
            float4 v = __ldg(gp + (size_t)rr * 32 + lane);
            acc.x += v.x; acc.y += v.y; acc.z += v.z; acc.w += v.w;
        }
    }
    float dv = d_dinv[gw];
    acc.x *= dv; acc.y *= dv; acc.z *= dv; acc.w *= dv;
    ((float4*)d_h)[(size_t)gw * 32 + lane] = acc;
}

// ---------------- edge head: 2 edges per thread, f32x2 packed ----------------
__global__ void k_logits(const float* __restrict__ Wfc, const float* __restrict__ bfc,
                         const int* __restrict__ row, const int* __restrict__ col,
                         const int* __restrict__ label, float* __restrict__ logits) {
    __shared__ __align__(16) float ws[NC * 256];
    __shared__ float bs[NC];
    __shared__ float red[256];
    const int tid = threadIdx.x;
    for (int i = tid; i < NC * 256; i += 256) ws[i] = Wfc[i];
    if (tid < NC) bs[tid] = bfc[tid];
    __syncthreads();

    const int e0 = blockIdx.x * 512 + tid;
    const int e1 = e0 + 256;
    const bool v0 = e0 < NE;
    const bool v1 = e1 < NE;
    int r0 = 0, c0 = 0, r1 = 0, c1 = 0;
    if (v0) { r0 = row[e0]; c0 = col[e0]; }
    if (v1) { r1 = row[e1]; c1 = col[e1]; }

    unsigned long long a0[NC], a1[NC];
#pragma unroll
    for (int cc = 0; cc < NC; cc++) { a0[cc] = 0ull; a1[cc] = 0ull; }

    const ulonglong2* pr0 = (const ulonglong2*)(d_h + (size_t)r0 * HF);
    const ulonglong2* pr1 = (const ulonglong2*)(d_h + (size_t)r1 * HF);
#pragma unroll
    for (int q = 0; q < 32; q++) {
        ulonglong2 xa = __ldg(pr0 + q);
        ulonglong2 xb = __ldg(pr1 + q);
#pragma unroll
        for (int cc = 0; cc < NC; cc++) {
            ulonglong2 wv = *(const ulonglong2*)&ws[cc * 256 + q * 4];
            FFMA2(a0[cc], xa.x, wv.x);
            FFMA2(a0[cc], xa.y, wv.y);
            FFMA2(a1[cc], xb.x, wv.x);
            FFMA2(a1[cc], xb.y, wv.y);
        }
    }
    const ulonglong2* pc0 = (const ulonglong2*)(d_h + (size_t)c0 * HF);
    const ulonglong2* pc1 = (const ulonglong2*)(d_h + (size_t)c1 * HF);
#pragma unroll
    for (int q = 0; q < 32; q++) {
        ulonglong2 xa = __ldg(pc0 + q);
        ulonglong2 xb = __ldg(pc1 + q);
#pragma unroll
        for (int cc = 0; cc < NC; cc++) {
            ulonglong2 wv = *(const ulonglong2*)&ws[cc * 256 + 128 + q * 4];
            FFMA2(a0[cc], xa.x, wv.x);
            FFMA2(a0[cc], xa.y, wv.y);
            FFMA2(a1[cc], xb.x, wv.x);
            FFMA2(a1[cc], xb.y, wv.y);
        }
    }

    float myloss = 0.f;
#pragma unroll
    for (int half = 0; half < 2; half++) {
        const unsigned long long* ap = half ? a1 : a0;
        const bool vv = half ? v1 : v0;
        const int ee = half ? e1 : e0;
        if (!vv) continue;
        float acc[NC];
#pragma unroll
        for (int cc = 0; cc < NC; cc++) {
            float lo, hi;
            asm("mov.b64 {%0, %1}, %2;" : "=f"(lo), "=f"(hi) : "l"(ap[cc]));
            acc[cc] = bs[cc] + lo + hi;
        }
        float m = acc[0];
#pragma unroll
        for (int cc = 1; cc < NC; cc++) m = fmaxf(m, acc[cc]);
        float s = 0.f;
#pragma unroll
        for (int cc = 0; cc < NC; cc++) s += expf(acc[cc] - m);
        float lse = m + logf(s);
        myloss += lse - acc[label[ee]];
        float* lp = logits + (size_t)ee * NC;
#pragma unroll
        for (int cc = 0; cc < NC; cc++) lp[cc] = acc[cc];
    }

    red[tid] = myloss;
    __syncthreads();
    for (int s2 = 128; s2 > 0; s2 >>= 1) {
        if (tid < s2) red[tid] += red[tid + s2];
        __syncthreads();
    }
    if (tid == 0) atomicAdd(&d_loss, red[0]);
}

__global__ void k_final(float* __restrict__ loss_out) {
    if (loss_out) loss_out[0] = d_loss * (1.0f / (float)NE);
}

// ---------------- launch ----------------
extern "C" void kernel_launch(void* const* d_in, const int* in_sizes, int n_in,
                              void* d_out, int out_size) {
    const float* feat = (const float*)d_in[0];
    const float* W1   = (const float*)d_in[1];
    const float* b1   = (const float*)d_in[2];
    const float* W2   = (const float*)d_in[3];
    const float* b2   = (const float*)d_in[4];
    const float* Wfc  = (const float*)d_in[5];
    const float* bfc  = (const float*)d_in[6];
    const int*   row  = (const int*)d_in[7];
    const int*   col  = (const int*)d_in[8];
    const int*   lab  = (const int*)d_in[9];

    float* out = (float*)d_out;
    float* lossp;
    float* logits;
    if (out_size == NE * NC + 1) { lossp = out; logits = out + 1; }
    else                         { lossp = nullptr; logits = out; }

    void* ph = nullptr;
    cudaGetSymbolAddress(&ph, d_h);
    const float* h1 = (const float*)ph;

    const int TB = 256;
    const int nb_nodes = (NN + TB - 1) / TB;
    const int nb_edges = (NE + TB - 1) / TB;
    const int nb_gemm  = (NN + 63) / 64;
    const int nb_aggr  = (NN * 32 + TB - 1) / TB;
    const int nb_log   = (NE + 511) / 512;

    k_init<<<nb_nodes, TB>>>();
    k_hist<<<nb_edges, TB>>>(row, col);
    k_dinv<<<nb_nodes, TB>>>();
    k_scan1<<<NBLK, 256>>>();
    k_scan2<<<1, 32>>>();
    k_scan3<<<nb_nodes, TB>>>();
    k_fill<<<nb_edges, TB>>>(row, col);

    // conv 1
    k_gemm<<<nb_gemm, TB>>>(feat, W1, b1);
    k_aggr<<<nb_aggr, TB>>>();            // -> d_h = h1

    // conv 2
    k_gemm<<<nb_gemm, TB>>>(h1, W2, b2);
    k_aggr<<<nb_aggr, TB>>>();            // -> d_h = h2

    // edge head
    k_logits<<<nb_log, TB>>>(Wfc, bfc, row, col, lab, logits);
    k_final<<<1, 1>>>(lossp);
}

// round 6
// speedup vs baseline: 1.0013x; 1.0013x over previous
#include <cuda_runtime.h>
#include <cstdint>

#define NN 50000
#define NE 600000
#define HF 128
#define NC 10
#define NBLK ((NN + 511) / 512)   // 98 scan blocks

// ---------------- scratch (static device globals; no allocation) ----------------
__device__ __align__(16) float d_g[(size_t)NN * HF];    // dinv*(xW^T+b)
__device__ __align__(16) float d_h[(size_t)NN * HF];    // conv output (h1 then h2)
__device__ int   d_deg[NN];      // row-degree + 1 (norm)
__device__ float d_dinv[NN];
__device__ int   d_cnt[NN];      // col histogram (CSR)
__device__ int   d_start[NN];    // CSR offsets
__device__ int   d_ptr[NN];      // CSR fill cursors
__device__ int   d_csr[NE];      // source row per CSR slot
__device__ int   d_bsum[128];    // scan block sums
__device__ int   d_boff[128];    // scan block offsets
__device__ float d_loss;

#define FFMA2(acc, a, b) asm("fma.rn.f32x2 %0, %1, %2, %0;" : "+l"(acc) : "l"(a), "l"(b))

// ---------------- init ----------------
__global__ void k_init() {
    int i = blockIdx.x * blockDim.x + threadIdx.x;
    if (i < NN) { d_deg[i] = 1; d_cnt[i] = 0; }
    if (i == 0) d_loss = 0.f;
}

// row-degree (norm) + col histogram (CSR) in one pass
__global__ void k_hist(const int* __restrict__ row, const int* __restrict__ col) {
    int e = blockIdx.x * blockDim.x + threadIdx.x;
    if (e < NE) {
        atomicAdd(&d_deg[row[e]], 1);
        atomicAdd(&d_cnt[col[e]], 1);
    }
}

__global__ void k_dinv() {
    int i = blockIdx.x * blockDim.x + threadIdx.x;
    if (i < NN) d_dinv[i] = rsqrtf((float)d_deg[i]);
}

// ---------------- multi-block exclusive scan of d_cnt ----------------
// phase 1: 98 blocks x 256 threads, 2 elements/thread -> local scan + block sums
__global__ void k_scan1() {
    __shared__ int wsum[8];
    const int t = threadIdx.x;
    const int base = blockIdx.x * 512 + t * 2;
    int c0 = (base < NN) ? d_cnt[base] : 0;
    int c1 = (base + 1 < NN) ? d_cnt[base + 1] : 0;
    int s = c0 + c1;
    int v = s;
#pragma unroll
    for (int o = 1; o < 32; o <<= 1) {
        int u = __shfl_up_sync(0xffffffffu, v, o);
        if ((t & 31) >= o) v += u;
    }
    if ((t & 31) == 31) wsum[t >> 5] = v;
    __syncthreads();
    if (t < 8) {
        int w = wsum[t];
#pragma unroll
        for (int o = 1; o < 8; o <<= 1) {
            int u = __shfl_up_sync(0xffu, w, o);
            if (t >= o) w += u;
        }
        wsum[t] = w;
    }
    __syncthreads();
    int pre = v - s + ((t >= 32) ? wsum[(t >> 5) - 1] : 0);
    if (base < NN) d_start[base] = pre;
    if (base + 1 < NN) d_start[base + 1] = pre + c0;
    if (t == 255) d_bsum[blockIdx.x] = wsum[7];
}

// phase 2: single warp scans the 98 block sums
__global__ void k_scan2() {
    const int l = threadIdx.x;
    int c[4];
    int s = 0;
#pragma unroll
    for (int i = 0; i < 4; i++) {
        int idx = l * 4 + i;
        c[i] = (idx < NBLK) ? d_bsum[idx] : 0;
        s += c[i];
    }
    int v = s;
#pragma unroll
    for (int o = 1; o < 32; o <<= 1) {
        int u = __shfl_up_sync(0xffffffffu, v, o);
        if (l >= o) v += u;
    }
    int ex = v - s;
#pragma unroll
    for (int i = 0; i < 4; i++) {
        int idx = l * 4 + i;
        if (idx < NBLK) d_boff[idx] = ex;
        ex += c[i];
    }
}

// phase 3: add block offsets, init fill cursors
__global__ void k_scan3() {
    int i = blockIdx.x * blockDim.x + threadIdx.x;
    if (i < NN) {
        int v = d_start[i] + d_boff[i >> 9];
        d_start[i] = v;
        d_ptr[i] = v;
    }
}

__global__ void k_fill(const int* __restrict__ row, const int* __restrict__ col) {
    int e = blockIdx.x * blockDim.x + threadIdx.x;
    if (e < NE) {
        int c = col[e];
        int slot = atomicAdd(&d_ptr[c], 1);
        d_csr[slot] = row[e];
    }
}

// ---------------- node GEMM (f32x2 packed): g = dinv * (x @ W^T + b) ----------------
// Block: 64 rows x 128 cols, 256 threads, thread = 8 rows x 4 cols.
// Shared staged as float2 k-pairs, stride 17 float2 (pad) per row.
__global__ void k_gemm(const float* __restrict__ x, const float* __restrict__ W,
                       const float* __restrict__ b) {
    __shared__ __align__(16) float2 xs2[64 * 17];
    __shared__ __align__(16) float2 ws2[128 * 17];
    const int tid = threadIdx.x;
    const int tc = tid & 31;
    const int tr = tid >> 5;
    const int rb = blockIdx.x * 64;

    unsigned long long acc2[8][4];
#pragma unroll
    for (int i = 0; i < 8; i++)
#pragma unroll
        for (int j = 0; j < 4; j++) acc2[i][j] = 0ull;

    for (int kc = 0; kc < HF; kc += 32) {
#pragma unroll
        for (int l = 0; l < 2; l++) {
            int idx = tid + l * 256;      // float4 index, 0..511
            int r = idx >> 3;
            int q = idx & 7;
            float4 v = make_float4(0.f, 0.f, 0.f, 0.f);
            if (rb + r < NN) v = *(const float4*)(x + (size_t)(rb + r) * HF + kc + q * 4);
            xs2[r * 17 + q * 2 + 0] = make_float2(v.x, v.y);
            xs2[r * 17 + q * 2 + 1] = make_float2(v.z, v.w);
        }
#pragma unroll
        for (int l = 0; l < 4; l++) {
            int idx = tid + l * 256;      // float4 index, 0..1023
            int t = idx >> 3;
            int q = idx & 7;
            float4 v = *(const float4*)(W + (size_t)t * HF + kc + q * 4);
            ws2[t * 17 + q * 2 + 0] = make_float2(v.x, v.y);
            ws2[t * 17 + q * 2 + 1] = make_float2(v.z, v.w);
        }
        __syncthreads();
#pragma unroll
        for (int kq = 0; kq < 16; kq++) {
            unsigned long long wv[4];
#pragma unroll
            for (int j = 0; j < 4; j++)
                wv[j] = *(const unsigned long long*)&ws2[(tc + 32 * j) * 17 + kq];
#pragma unroll
            for (int i = 0; i < 8; i++) {
                unsigned long long xv =
                    *(const unsigned long long*)&xs2[(tr * 8 + i) * 17 + kq];
#pragma unroll
                for (int j = 0; j < 4; j++) FFMA2(acc2[i][j], xv, wv[j]);
            }
        }
        __syncthreads();
    }

#pragma unroll
    for (int i = 0; i < 8; i++) {
        int r = rb + tr * 8 + i;
        if (r >= NN) break;
        float dv = d_dinv[r];
#pragma unroll
        for (int j = 0; j < 4; j++) {
            int c0 = tc + 32 * j;
            float lo, hi;
            asm("mov.b64 {%0, %1}, %2;" : "=f"(lo), "=f"(hi) : "l"(acc2[i][j]));
            d_g[(size_t)r * HF + c0] = dv * (lo + hi + b[c0]);
        }
    }
}

// ---------------- CSR aggregate: h[n] = dinv[n] * (g[n] + sum_{e: col=n} g[row_e]) ----------------
__global__ void k_aggr() {
    int gw = (blockIdx.x * blockDim.x + threadIdx.x) >> 5;
    if (gw >= NN) return;
    const int lane = threadIdx.x & 31;
    const int s = d_start[gw];
    const int cnt = d_cnt[gw];
    const float4* gp = (const float4*)d_g;

    float4 acc = __ldg(gp + (size_t)gw * 32 + lane);   // self loop
    for (int j0 = 0; j0 < cnt; j0 += 32) {
        int r = 0;
        if (j0 + lane < cnt) r = __ldg(d_csr + s + j0 + lane);
        int m = min(32, cnt - j0);
        int k = 0;
        for (; k + 4 <= m; k += 4) {
            int r0 = __shfl_sync(0xffffffffu, r, k + 0);
            int r1 = __shfl_sync(0xffffffffu, r, k + 1);
            int r2 = __shfl_sync(0xffffffffu, r, k + 2);
            int r3 = __shfl_sync(0xffffffffu, r, k + 3);
            float4 v0 = __ldg(gp + (size_t)r0 * 32 + lane);
            float4 v1 = __ldg(gp + (size_t)r1 * 32 + lane);
            float4 v2 = __ldg(gp + (size_t)r2 * 32 + lane);
            float4 v3 = __ldg(gp + (size_t)r3 * 32 + lane);
            acc.x += v0.x + v1.x + v2.x + v3.x;
            acc.y += v0.y + v1.y + v2.y + v3.y;
            acc.z += v0.z + v1.z + v2.z + v3.z;
            acc.w += v0.w + v1.w + v2.w + v3.w;
        }
        for (; k < m; k++) {
            int rr = __shfl_sync(0xffffffffu, r, k);
            float4 v = __ldg(gp + (size_t)rr * 32 + lane);
            acc.x += v.x; acc.y += v.y; acc.z += v.z; acc.w += v.w;
        }
    }
    float dv = d_dinv[gw];
    acc.x *= dv; acc.y *= dv; acc.z *= dv; acc.w *= dv;
    ((float4*)d_h)[(size_t)gw * 32 + lane] = acc;
}

// ---------------- edge head: 2 edges per thread, f32x2 packed ----------------
__global__ void k_logits(const float* __restrict__ Wfc, const float* __restrict__ bfc,
                         const int* __restrict__ row, const int* __restrict__ col,
                         const int* __restrict__ label, float* __restrict__ logits) {
    __shared__ __align__(16) float ws[NC * 256];
    __shared__ float bs[NC];
    __shared__ float red[256];
    const int tid = threadIdx.x;
    for (int i = tid; i < NC * 256; i += 256) ws[i] = Wfc[i];
    if (tid < NC) bs[tid] = bfc[tid];
    __syncthreads();

    const int e0 = blockIdx.x * 512 + tid;
    const int e1 = e0 + 256;
    const bool v0 = e0 < NE;
    const bool v1 = e1 < NE;
    int r0 = 0, c0 = 0, r1 = 0, c1 = 0;
    if (v0) { r0 = row[e0]; c0 = col[e0]; }
    if (v1) { r1 = row[e1]; c1 = col[e1]; }

    unsigned long long a0[NC], a1[NC];
#pragma unroll
    for (int cc = 0; cc < NC; cc++) { a0[cc] = 0ull; a1[cc] = 0ull; }

    const ulonglong2* pr0 = (const ulonglong2*)(d_h + (size_t)r0 * HF);
    const ulonglong2* pr1 = (const ulonglong2*)(d_h + (size_t)r1 * HF);
#pragma unroll
    for (int q = 0; q < 32; q++) {
        ulonglong2 xa = __ldg(pr0 + q);
        ulonglong2 xb = __ldg(pr1 + q);
#pragma unroll
        for (int cc = 0; cc < NC; cc++) {
            ulonglong2 wv = *(const ulonglong2*)&ws[cc * 256 + q * 4];
            FFMA2(a0[cc], xa.x, wv.x);
            FFMA2(a0[cc], xa.y, wv.y);
            FFMA2(a1[cc], xb.x, wv.x);
            FFMA2(a1[cc], xb.y, wv.y);
        }
    }
    const ulonglong2* pc0 = (const ulonglong2*)(d_h + (size_t)c0 * HF);
    const ulonglong2* pc1 = (const ulonglong2*)(d_h + (size_t)c1 * HF);
#pragma unroll
    for (int q = 0; q < 32; q++) {
        ulonglong2 xa = __ldg(pc0 + q);
        ulonglong2 xb = __ldg(pc1 + q);
#pragma unroll
        for (int cc = 0; cc < NC; cc++) {
            ulonglong2 wv = *(const ulonglong2*)&ws[cc * 256 + 128 + q * 4];
            FFMA2(a0[cc], xa.x, wv.x);
            FFMA2(a0[cc], xa.y, wv.y);
            FFMA2(a1[cc], xb.x, wv.x);
            FFMA2(a1[cc], xb.y, wv.y);
        }
    }

    float myloss = 0.f;
#pragma unroll
    for (int half = 0; half < 2; half++) {
        const unsigned long long* ap = half ? a1 : a0;
        const bool vv = half ? v1 : v0;
        const int ee = half ? e1 : e0;
        if (!vv) continue;
        float acc[NC];
#pragma unroll
        for (int cc = 0; cc < NC; cc++) {
            float lo, hi;
            asm("mov.b64 {%0, %1}, %2;" : "=f"(lo), "=f"(hi) : "l"(ap[cc]));
            acc[cc] = bs[cc] + lo + hi;
        }
        float m = acc[0];
#pragma unroll
        for (int cc = 1; cc < NC; cc++) m = fmaxf(m, acc[cc]);
        float s = 0.f;
#pragma unroll
        for (int cc = 0; cc < NC; cc++) s += expf(acc[cc] - m);
        float lse = m + logf(s);
        myloss += lse - acc[label[ee]];
        float* lp = logits + (size_t)ee * NC;
#pragma unroll
        for (int cc = 0; cc < NC; cc++) lp[cc] = acc[cc];
    }

    red[tid] = myloss;
    __syncthreads();
    for (int s2 = 128; s2 > 0; s2 >>= 1) {
        if (tid < s2) red[tid] += red[tid + s2];
        __syncthreads();
    }
    if (tid == 0) atomicAdd(&d_loss, red[0]);
}

__global__ void k_final(float* __restrict__ loss_out) {
    if (loss_out) loss_out[0] = d_loss * (1.0f / (float)NE);
}

// ---------------- launch ----------------
extern "C" void kernel_launch(void* const* d_in, const int* in_sizes, int n_in,
                              void* d_out, int out_size) {
    const float* feat = (const float*)d_in[0];
    const float* W1   = (const float*)d_in[1];
    const float* b1   = (const float*)d_in[2];
    const float* W2   = (const float*)d_in[3];
    const float* b2   = (const float*)d_in[4];
    const float* Wfc  = (const float*)d_in[5];
    const float* bfc  = (const float*)d_in[6];
    const int*   row  = (const int*)d_in[7];
    const int*   col  = (const int*)d_in[8];
    const int*   lab  = (const int*)d_in[9];

    float* out = (float*)d_out;
    float* lossp;
    float* logits;
    if (out_size == NE * NC + 1) { lossp = out; logits = out + 1; }
    else                         { lossp = nullptr; logits = out; }

    void* ph = nullptr;
    cudaGetSymbolAddress(&ph, d_h);
    const float* h1 = (const float*)ph;

    const int TB = 256;
    const int nb_nodes = (NN + TB - 1) / TB;
    const int nb_edges = (NE + TB - 1) / TB;
    const int nb_gemm  = (NN + 63) / 64;
    const int nb_aggr  = (NN * 32 + TB - 1) / TB;
    const int nb_log   = (NE + 511) / 512;

    k_init<<<nb_nodes, TB>>>();
    k_hist<<<nb_edges, TB>>>(row, col);
    k_dinv<<<nb_nodes, TB>>>();
    k_scan1<<<NBLK, 256>>>();
    k_scan2<<<1, 32>>>();
    k_scan3<<<nb_nodes, TB>>>();
    k_fill<<<nb_edges, TB>>>(row, col);

    // conv 1
    k_gemm<<<nb_gemm, TB>>>(feat, W1, b1);
    k_aggr<<<nb_aggr, TB>>>();            // -> d_h = h1

    // conv 2
    k_gemm<<<nb_gemm, TB>>>(h1, W2, b2);
    k_aggr<<<nb_aggr, TB>>>();            // -> d_h = h2

    // edge head
    k_logits<<<nb_log, TB>>>(Wfc, bfc, row, col, lab, logits);
    k_final<<<1, 1>>>(lossp);
}

// round 7
// speedup vs baseline: 1.0018x; 1.0005x over previous
#include <cuda_runtime.h>
#include <cstdint>

#define NN 50000
#define NE 600000
#define HF 128
#define NC 10
#define NBLK ((NN + 511) / 512)   // 98 scan blocks

// ---------------- scratch (static device globals; no allocation) ----------------
__device__ __align__(16) float d_g[(size_t)NN * HF];    // dinv*(xW^T+b)
__device__ __align__(16) float d_h[(size_t)NN * HF];    // conv output (h1 then h2)
__device__ int   d_deg[NN];      // row-degree + 1 (norm)
__device__ float d_dinv[NN];
__device__ int   d_cnt[NN];      // col histogram (CSR)
__device__ int   d_start[NN];    // CSR offsets
__device__ int   d_ptr[NN];      // CSR fill cursors
__device__ int   d_csr[NE];      // source row per CSR slot
__device__ int   d_bsum[128];    // scan block sums
__device__ int   d_boff[128];    // scan block offsets
__device__ float d_loss;

#define FFMA2(acc, a, b) asm("fma.rn.f32x2 %0, %1, %2, %0;" : "+l"(acc) : "l"(a), "l"(b))

// ---------------- init ----------------
__global__ void k_init() {
    int i = blockIdx.x * blockDim.x + threadIdx.x;
    if (i < NN) { d_deg[i] = 1; d_cnt[i] = 0; }
    if (i == 0) d_loss = 0.f;
}

// row-degree (norm) + col histogram (CSR) in one pass
__global__ void k_hist(const int* __restrict__ row, const int* __restrict__ col) {
    int e = blockIdx.x * blockDim.x + threadIdx.x;
    if (e < NE) {
        atomicAdd(&d_deg[row[e]], 1);
        atomicAdd(&d_cnt[col[e]], 1);
    }
}

__global__ void k_dinv() {
    int i = blockIdx.x * blockDim.x + threadIdx.x;
    if (i < NN) d_dinv[i] = rsqrtf((float)d_deg[i]);
}

// ---------------- multi-block exclusive scan of d_cnt ----------------
// phase 1: 98 blocks x 256 threads, 2 elements/thread -> local scan + block sums
__global__ void k_scan1() {
    __shared__ int wsum[8];
    const int t = threadIdx.x;
    const int base = blockIdx.x * 512 + t * 2;
    int c0 = (base < NN) ? d_cnt[base] : 0;
    int c1 = (base + 1 < NN) ? d_cnt[base + 1] : 0;
    int s = c0 + c1;
    int v = s;
#pragma unroll
    for (int o = 1; o < 32; o <<= 1) {
        int u = __shfl_up_sync(0xffffffffu, v, o);
        if ((t & 31) >= o) v += u;
    }
    if ((t & 31) == 31) wsum[t >> 5] = v;
    __syncthreads();
    if (t < 8) {
        int w = wsum[t];
#pragma unroll
        for (int o = 1; o < 8; o <<= 1) {
            int u = __shfl_up_sync(0xffu, w, o);
            if (t >= o) w += u;
        }
        wsum[t] = w;
    }
    __syncthreads();
    int pre = v - s + ((t >= 32) ? wsum[(t >> 5) - 1] : 0);
    if (base < NN) d_start[base] = pre;
    if (base + 1 < NN) d_start[base + 1] = pre + c0;
    if (t == 255) d_bsum[blockIdx.x] = wsum[7];
}

// phase 2: single warp scans the 98 block sums
__global__ void k_scan2() {
    const int l = threadIdx.x;
    int c[4];
    int s = 0;
#pragma unroll
    for (int i = 0; i < 4; i++) {
        int idx = l * 4 + i;
        c[i] = (idx < NBLK) ? d_bsum[idx] : 0;
        s += c[i];
    }
    int v = s;
#pragma unroll
    for (int o = 1; o < 32; o <<= 1) {
        int u = __shfl_up_sync(0xffffffffu, v, o);
        if (l >= o) v += u;
    }
    int ex = v - s;
#pragma unroll
    for (int i = 0; i < 4; i++) {
        int idx = l * 4 + i;
        if (idx < NBLK) d_boff[idx] = ex;
        ex += c[i];
    }
}

// phase 3: add block offsets, init fill cursors
__global__ void k_scan3() {
    int i = blockIdx.x * blockDim.x + threadIdx.x;
    if (i < NN) {
        int v = d_start[i] + d_boff[i >> 9];
        d_start[i] = v;
        d_ptr[i] = v;
    }
}

__global__ void k_fill(const int* __restrict__ row, const int* __restrict__ col) {
    int e = blockIdx.x * blockDim.x + threadIdx.x;
    if (e < NE) {
        int c = col[e];
        int slot = atomicAdd(&d_ptr[c], 1);
        d_csr[slot] = row[e];
    }
}

// ---------------- node GEMM (f32x2 packed): g = dinv * (x @ W^T + b) ----------------
// Block: 64 rows x 128 cols, 256 threads, thread = 8 rows x 4 cols.
// Shared staged as float2 k-pairs, stride 17 float2 (pad) per row.
__global__ void k_gemm(const float* __restrict__ x, const float* __restrict__ W,
                       const float* __restrict__ b) {
    __shared__ __align__(16) float2 xs2[64 * 17];
    __shared__ __align__(16) float2 ws2[128 * 17];
    const int tid = threadIdx.x;
    const int tc = tid & 31;
    const int tr = tid >> 5;
    const int rb = blockIdx.x * 64;

    unsigned long long acc2[8][4];
#pragma unroll
    for (int i = 0; i < 8; i++)
#pragma unroll
        for (int j = 0; j < 4; j++) acc2[i][j] = 0ull;

    for (int kc = 0; kc < HF; kc += 32) {
#pragma unroll
        for (int l = 0; l < 2; l++) {
            int idx = tid + l * 256;      // float4 index, 0..511
            int r = idx >> 3;
            int q = idx & 7;
            float4 v = make_float4(0.f, 0.f, 0.f, 0.f);
            if (rb + r < NN) v = *(const float4*)(x + (size_t)(rb + r) * HF + kc + q * 4);
            xs2[r * 17 + q * 2 + 0] = make_float2(v.x, v.y);
            xs2[r * 17 + q * 2 + 1] = make_float2(v.z, v.w);
        }
#pragma unroll
        for (int l = 0; l < 4; l++) {
            int idx = tid + l * 256;      // float4 index, 0..1023
            int t = idx >> 3;
            int q = idx & 7;
            float4 v = *(const float4*)(W + (size_t)t * HF + kc + q * 4);
            ws2[t * 17 + q * 2 + 0] = make_float2(v.x, v.y);
            ws2[t * 17 + q * 2 + 1] = make_float2(v.z, v.w);
        }
        __syncthreads();
#pragma unroll
        for (int kq = 0; kq < 16; kq++) {
            unsigned long long wv[4];
#pragma unroll
            for (int j = 0; j < 4; j++)
                wv[j] = *(const unsigned long long*)&ws2[(tc + 32 * j) * 17 + kq];
#pragma unroll
            for (int i = 0; i < 8; i++) {
                unsigned long long xv =
                    *(const unsigned long long*)&xs2[(tr * 8 + i) * 17 + kq];
#pragma unroll
                for (int j = 0; j < 4; j++) FFMA2(acc2[i][j], xv, wv[j]);
            }
        }
        __syncthreads();
    }

#pragma unroll
    for (int i = 0; i < 8; i++) {
        int r = rb + tr * 8 + i;
        if (r >= NN) break;
        float dv = d_dinv[r];
#pragma unroll
        for (int j = 0; j < 4; j++) {
            int c0 = tc + 32 * j;
            float lo, hi;
            asm("mov.b64 {%0, %1}, %2;" : "=f"(lo), "=f"(hi) : "l"(acc2[i][j]));
            d_g[(size_t)r * HF + c0] = dv * (lo + hi + b[c0]);
        }
    }
}

// ---------------- CSR aggregate: h[n] = dinv[n] * (g[n] + sum_{e: col=n} g[row_e]) ----------------
__global__ void k_aggr() {
    int gw = (blockIdx.x * blockDim.x + threadIdx.x) >> 5;
    if (gw >= NN) return;
    const int lane = threadIdx.x & 31;
    const int s = d_start[gw];
    const int cnt = d_cnt[gw];
    const float4* gp = (const float4*)d_g;

    float4 acc = __ldg(gp + (size_t)gw * 32 + lane);   // self loop
    for (int j0 = 0; j0 < cnt; j0 += 32) {
        int r = 0;
        if (j0 + lane < cnt) r = __ldg(d_csr + s + j0 + lane);
        int m = min(32, cnt - j0);
        int k = 0;
        for (; k + 4 <= m; k += 4) {
            int r0 = __shfl_sync(0xffffffffu, r, k + 0);
            int r1 = __shfl_sync(0xffffffffu, r, k + 1);
            int r2 = __shfl_sync(0xffffffffu, r, k + 2);
            int r3 = __shfl_sync(0xffffffffu, r, k + 3);
            float4 v0 = __ldg(gp + (size_t)r0 * 32 + lane);
            float4 v1 = __ldg(gp + (size_t)r1 * 32 + lane);
            float4 v2 = __ldg(gp + (size_t)r2 * 32 + lane);
            float4 v3 = __ldg(gp + (size_t)r3 * 32 + lane);
            acc.x += v0.x + v1.x + v2.x + v3.x;
            acc.y += v0.y + v1.y + v2.y + v3.y;
            acc.z += v0.z + v1.z + v2.z + v3.z;
            acc.w += v0.w + v1.w + v2.w + v3.w;
        }
        for (; k < m; k++) {
            int rr = __shfl_sync(0xffffffffu, r, k);
            float4 v = __ldg(gp + (size_t)rr * 32 + lane);
            acc.x += v.x; acc.y += v.y; acc.z += v.z; acc.w += v.w;
        }
    }
    float dv = d_dinv[gw];
    acc.x *= dv; acc.y *= dv; acc.z *= dv; acc.w *= dv;
    ((float4*)d_h)[(size_t)gw * 32 + lane] = acc;
}

// ---------------- edge head: 2 edges per thread, f32x2 packed ----------------
__global__ void k_logits(const float* __restrict__ Wfc, const float* __restrict__ bfc,
                         const int* __restrict__ row, const int* __restrict__ col,
                         const int* __restrict__ label, float* __restrict__ logits) {
    __shared__ __align__(16) float ws[NC * 256];
    __shared__ float bs[NC];
    __shared__ float red[256];
    const int tid = threadIdx.x;
    for (int i = tid; i < NC * 256; i += 256) ws[i] = Wfc[i];
    if (tid < NC) bs[tid] = bfc[tid];
    __syncthreads();

    const int e0 = blockIdx.x * 512 + tid;
    const int e1 = e0 + 256;
    const bool v0 = e0 < NE;
    const bool v1 = e1 < NE;
    int r0 = 0, c0 = 0, r1 = 0, c1 = 0;
    if (v0) { r0 = row[e0]; c0 = col[e0]; }
    if (v1) { r1 = row[e1]; c1 = col[e1]; }

    unsigned long long a0[NC], a1[NC];
#pragma unroll
    for (int cc = 0; cc < NC; cc++) { a0[cc] = 0ull; a1[cc] = 0ull; }

    const ulonglong2* pr0 = (const ulonglong2*)(d_h + (size_t)r0 * HF);
    const ulonglong2* pr1 = (const ulonglong2*)(d_h + (size_t)r1 * HF);
#pragma unroll
    for (int q = 0; q < 32; q++) {
        ulonglong2 xa = __ldg(pr0 + q);
        ulonglong2 xb = __ldg(pr1 + q);
#pragma unroll
        for (int cc = 0; cc < NC; cc++) {
            ulonglong2 wv = *(const ulonglong2*)&ws[cc * 256 + q * 4];
            FFMA2(a0[cc], xa.x, wv.x);
            FFMA2(a0[cc], xa.y, wv.y);
            FFMA2(a1[cc], xb.x, wv.x);
            FFMA2(a1[cc], xb.y, wv.y);
        }
    }
    const ulonglong2* pc0 = (const ulonglong2*)(d_h + (size_t)c0 * HF);
    const ulonglong2* pc1 = (const ulonglong2*)(d_h + (size_t)c1 * HF);
#pragma unroll
    for (int q = 0; q < 32; q++) {
        ulonglong2 xa = __ldg(pc0 + q);
        ulonglong2 xb = __ldg(pc1 + q);
#pragma unroll
        for (int cc = 0; cc < NC; cc++) {
            ulonglong2 wv = *(const ulonglong2*)&ws[cc * 256 + 128 + q * 4];
            FFMA2(a0[cc], xa.x, wv.x);
            FFMA2(a0[cc], xa.y, wv.y);
            FFMA2(a1[cc], xb.x, wv.x);
            FFMA2(a1[cc], xb.y, wv.y);
        }
    }

    float myloss = 0.f;
#pragma unroll
    for (int half = 0; half < 2; half++) {
        const unsigned long long* ap = half ? a1 : a0;
        const bool vv = half ? v1 : v0;
        const int ee = half ? e1 : e0;
        if (!vv) continue;
        float acc[NC];
#pragma unroll
        for (int cc = 0; cc < NC; cc++) {
            float lo, hi;
            asm("mov.b64 {%0, %1}, %2;" : "=f"(lo), "=f"(hi) : "l"(ap[cc]));
            acc[cc] = bs[cc] + lo + hi;
        }
        float m = acc[0];
#pragma unroll
        for (int cc = 1; cc < NC; cc++) m = fmaxf(m, acc[cc]);
        float s = 0.f;
#pragma unroll
        for (int cc = 0; cc < NC; cc++) s += expf(acc[cc] - m);
        float lse = m + logf(s);
        myloss += lse - acc[label[ee]];
        float* lp = logits + (size_t)ee * NC;
#pragma unroll
        for (int cc = 0; cc < NC; cc++) lp[cc] = acc[cc];
    }

    red[tid] = myloss;
    __syncthreads();
    for (int s2 = 128; s2 > 0; s2 >>= 1) {
        if (tid < s2) red[tid] += red[tid + s2];
        __syncthreads();
    }
    if (tid == 0) atomicAdd(&d_loss, red[0]);
}

__global__ void k_final(float* __restrict__ loss_out) {
    if (loss_out) loss_out[0] = d_loss * (1.0f / (float)NE);
}

// ---------------- launch ----------------
extern "C" void kernel_launch(void* const* d_in, const int* in_sizes, int n_in,
                              void* d_out, int out_size) {
    const float* feat = (const float*)d_in[0];
    const float* W1   = (const float*)d_in[1];
    const float* b1   = (const float*)d_in[2];
    const float* W2   = (const float*)d_in[3];
    const float* b2   = (const float*)d_in[4];
    const float* Wfc  = (const float*)d_in[5];
    const float* bfc  = (const float*)d_in[6];
    const int*   row  = (const int*)d_in[7];
    const int*   col  = (const int*)d_in[8];
    const int*   lab  = (const int*)d_in[9];

    float* out = (float*)d_out;
    float* lossp;
    float* logits;
    if (out_size == NE * NC + 1) { lossp = out; logits = out + 1; }
    else                         { lossp = nullptr; logits = out; }

    void* ph = nullptr;
    cudaGetSymbolAddress(&ph, d_h);
    const float* h1 = (const float*)ph;

    const int TB = 256;
    const int nb_nodes = (NN + TB - 1) / TB;
    const int nb_edges = (NE + TB - 1) / TB;
    const int nb_gemm  = (NN + 63) / 64;
    const int nb_aggr  = (NN * 32 + TB - 1) / TB;
    const int nb_log   = (NE + 511) / 512;

    k_init<<<nb_nodes, TB>>>();
    k_hist<<<nb_edges, TB>>>(row, col);
    k_dinv<<<nb_nodes, TB>>>();
    k_scan1<<<NBLK, 256>>>();
    k_scan2<<<1, 32>>>();
    k_scan3<<<nb_nodes, TB>>>();
    k_fill<<<nb_edges, TB>>>(row, col);

    // conv 1
    k_gemm<<<nb_gemm, TB>>>(feat, W1, b1);
    k_aggr<<<nb_aggr, TB>>>();            // -> d_h = h1

    // conv 2
    k_gemm<<<nb_gemm, TB>>>(h1, W2, b2);
    k_aggr<<<nb_aggr, TB>>>();            // -> d_h = h2

    // edge head
    k_logits<<<nb_log, TB>>>(Wfc, bfc, row, col, lab, logits);
    k_final<<<1, 1>>>(lossp);
}